// round 8
// baseline (speedup 1.0000x reference)
#include <cuda_runtime.h>
#include <math.h>
#include <float.h>

#define NPTS 8192
#define KNN  20

// ------------------------- scratch (__device__ globals, no allocation) ------
__device__ float g_D[(size_t)NPTS * NPTS];   // 256 MB dist matrix
__device__ float g_x2[NPTS];
__device__ int   g_idx[NPTS * KNN];
__device__ float g_cat[NPTS * 420];          // x1|x2|x3 concatenated (60|120|240)
__device__ float g_h1[NPTS * 1024];
__device__ float g_h2[NPTS * 256];
__device__ float g_h3[NPTS * 128];

// ------------------------- squared norms ------------------------------------
// Hybrid emulation of XLA GPU's reduction emitters for sum(x*x, -1), with
// SEPARATELY ROUNDED mul then add (NVVM default: no contraction):
//   C small (3)    : loop-fusion path, one thread per row, sequential
//                    ascending adds:  s = fadd(s, fmul(v,v)).
//   C large (60/120): row-reduction path, one warp per row; lane t
//                    accumulates c = t, t+32, ... sequentially, then a
//                    full-warp shuffle-DOWN tree (offsets 16,8,4,2,1).
__global__ void sqnorm_seq_kernel(const float* __restrict__ X, int ld, int C,
                                  float* __restrict__ x2) {
    int i = blockIdx.x * blockDim.x + threadIdx.x;
    if (i >= NPTS) return;
    const float* r = X + (size_t)i * ld;
    float s = 0.f;
    for (int c = 0; c < C; ++c)
        s = __fadd_rn(s, __fmul_rn(r[c], r[c]));
    x2[i] = s;
}

__global__ void sqnorm_warp_kernel(const float* __restrict__ X, int ld, int C,
                                   float* __restrict__ x2) {
    const int lane = threadIdx.x & 31;
    const int row  = (blockIdx.x * blockDim.x + threadIdx.x) >> 5;
    if (row >= NPTS) return;

    const float* r = X + (size_t)row * ld;
    float s = 0.f;
    for (int c = lane; c < C; c += 32)
        s = __fadd_rn(s, __fmul_rn(r[c], r[c]));
#pragma unroll
    for (int off = 16; off > 0; off >>= 1)
        s = __fadd_rn(s, __shfl_down_sync(0xffffffffu, s, off));
    if (lane == 0) x2[row] = s;
}

// ------------------------- tiled fp32 GEMM ----------------------------------
// DIST  : C[i,j] = (x2[i] + x2[j]) - 2*dot(A_i, B_j)    (2*dot exact; the
//         sub is the only rounding, identical whether contracted or not)
// !DIST : C[i,j] = relu(dot(A_i, W[:,j]) + bias[j])
// dot = increasing-k single-accumulator FFMA chain (cuBLAS SGEMM order).
#define BM 128
#define BN 128
#define BK 16

template <bool DIST>
__global__ void gemm_kernel(const float* __restrict__ A, int lda,
                            const float* __restrict__ B, int ldb,
                            const float* __restrict__ bias,
                            const float* __restrict__ x2v,
                            float* __restrict__ Cout, int ldc,
                            int N, int K) {
    __shared__ float As[BK][BM + 4];
    __shared__ float Bs[BK][BN + 4];

    const int tid = threadIdx.x;          // 256
    const int tx = tid & 15;
    const int ty = tid >> 4;
    const int i0 = blockIdx.y * BM;
    const int j0 = blockIdx.x * BN;

    float acc[8][8];
#pragma unroll
    for (int u = 0; u < 8; ++u)
#pragma unroll
        for (int v = 0; v < 8; ++v) acc[u][v] = 0.f;

    for (int kk = 0; kk < K; kk += BK) {
        // A tile (M rows always full: 8192)
        for (int e = tid; e < BM * BK; e += 256) {
            int r = e >> 4, c = e & 15;
            float v = 0.f;
            if (kk + c < K) v = A[(size_t)(i0 + r) * lda + kk + c];
            As[c][r] = v;
        }
        // B tile
        if (DIST) {
            for (int e = tid; e < BN * BK; e += 256) {
                int r = e >> 4, c = e & 15;
                float v = 0.f;
                if (kk + c < K) v = B[(size_t)(j0 + r) * ldb + kk + c];
                Bs[c][r] = v;
            }
        } else {
            for (int e = tid; e < BK * BN; e += 256) {
                int r = e >> 7, c = e & 127;
                float v = 0.f;
                if (kk + r < K && j0 + c < N)
                    v = B[(size_t)(kk + r) * ldb + j0 + c];
                Bs[r][c] = v;
            }
        }
        __syncthreads();

#pragma unroll
        for (int k = 0; k < BK; ++k) {
            float a[8], b[8];
            *(float4*)&a[0] = *(const float4*)&As[k][ty * 8];
            *(float4*)&a[4] = *(const float4*)&As[k][ty * 8 + 4];
            *(float4*)&b[0] = *(const float4*)&Bs[k][tx * 8];
            *(float4*)&b[4] = *(const float4*)&Bs[k][tx * 8 + 4];
#pragma unroll
            for (int u = 0; u < 8; ++u)
#pragma unroll
                for (int v = 0; v < 8; ++v)
                    acc[u][v] = fmaf(a[u], b[v], acc[u][v]);
        }
        __syncthreads();
    }

#pragma unroll
    for (int u = 0; u < 8; ++u) {
        int i = i0 + ty * 8 + u;
#pragma unroll
        for (int v = 0; v < 8; ++v) {
            int j = j0 + tx * 8 + v;
            if (j < N) {
                float r;
                if (DIST) {
                    float t = __fadd_rn(x2v[i], x2v[j]);
                    r = __fsub_rn(t, __fmul_rn(2.f, acc[u][v]));
                } else {
                    r = fmaxf(__fadd_rn(acc[u][v], bias[j]), 0.f);
                }
                Cout[(size_t)i * ldc + j] = r;
            }
        }
    }
}

// ------------------------- top-20 selection (warp per row) ------------------
// Reproduces jax.lax.top_k(-dist, 20) ordering: ascending dist, ties -> lower
// index first (candidates scanned in increasing j; strict '<' comparisons).
__global__ void topk_kernel(const float* __restrict__ D, int* __restrict__ out) {
    __shared__ float sd[8][KNN];
    __shared__ int   si[8][KNN];

    const int lane = threadIdx.x & 31;
    const int wloc = threadIdx.x >> 5;
    const int row  = (blockIdx.x * blockDim.x + threadIdx.x) >> 5;

    if (lane < KNN) { sd[wloc][lane] = FLT_MAX; si[wloc][lane] = 0x7fffffff; }
    __syncwarp();

    const float* r = D + (size_t)row * NPTS;
    float thresh = FLT_MAX;

    for (int base = 0; base < NPTS; base += 32) {
        float d = r[base + lane];
        unsigned m = __ballot_sync(0xffffffffu, d < thresh);
        while (m) {
            int src = __ffs(m) - 1;
            m &= m - 1;
            float dc = __shfl_sync(0xffffffffu, d, src);
            int   jc = base + src;
            if (lane == 0) {
                if (dc < sd[wloc][KNN - 1]) {
                    int p = KNN - 1;
                    while (p > 0 && sd[wloc][p - 1] > dc) {
                        sd[wloc][p] = sd[wloc][p - 1];
                        si[wloc][p] = si[wloc][p - 1];
                        --p;
                    }
                    sd[wloc][p] = dc;
                    si[wloc][p] = jc;
                }
            }
            __syncwarp();
            thresh = sd[wloc][KNN - 1];
        }
    }
    if (lane < KNN) out[row * KNN + lane] = si[wloc][lane];
}

// ------------------------- erosion EdgeConv ---------------------------------
// out[i, f*C + c] = min_k ( Xin[idx[i,k], c] - w[f,k,c] )   (sub + min: exact)
__global__ void erode_kernel(const float* __restrict__ Xin, int ldin,
                             const int* __restrict__ idx,
                             const float* __restrict__ w,
                             float* __restrict__ out, int ldout,
                             int F, int C) {
    __shared__ float nb[KNN * 120];    // max C = 120
    const int i = blockIdx.x;
    const int* ip = idx + i * KNN;

    for (int e = threadIdx.x; e < KNN * C; e += blockDim.x) {
        int k = e / C, c = e - k * C;
        nb[e] = Xin[(size_t)ip[k] * ldin + c];
    }
    __syncthreads();

    for (int e = threadIdx.x; e < F * C; e += blockDim.x) {
        int f = e / C, c = e - f * C;
        float mn = FLT_MAX;
        const float* wf = w + (size_t)f * KNN * C + c;
#pragma unroll 4
        for (int k = 0; k < KNN; ++k)
            mn = fminf(mn, __fsub_rn(nb[k * C + c], wf[k * C]));
        out[(size_t)i * ldout + e] = mn;
    }
}

// ------------------------- final linear + log_softmax -----------------------
__global__ void head_kernel(const float* __restrict__ H,
                            const float* __restrict__ wo,
                            const float* __restrict__ bo,
                            float* __restrict__ out) {
    __shared__ float h[128];
    __shared__ float lg[40];
    __shared__ float s_lse;
    const int i = blockIdx.x;
    const int t = threadIdx.x;              // 128 threads

    h[t] = H[(size_t)i * 128 + t];
    __syncthreads();

    if (t < 40) {
        float s = 0.f;                       // dot from 0 (ref: GEMM then +b)
#pragma unroll 8
        for (int k = 0; k < 128; ++k) s = fmaf(h[k], wo[k * 40 + t], s);
        lg[t] = __fadd_rn(s, bo[t]);
    }
    __syncthreads();

    if (t == 0) {
        float m = -FLT_MAX;
        for (int n = 0; n < 40; ++n) m = fmaxf(m, lg[n]);
        float s = 0.f;
        for (int n = 0; n < 40; ++n) s = __fadd_rn(s, expf(__fsub_rn(lg[n], m)));
        s_lse = __fadd_rn(m, logf(s));
    }
    __syncthreads();

    if (t < 40) out[(size_t)i * 40 + t] = __fsub_rn(lg[t], s_lse);
}

// ------------------------- launch sequence ----------------------------------
extern "C" void kernel_launch(void* const* d_in, const int* in_sizes, int n_in,
                              void* d_out, int out_size) {
    const float* x      = (const float*)d_in[0];
    const float* w1     = (const float*)d_in[1];
    const float* w2     = (const float*)d_in[2];
    const float* w3     = (const float*)d_in[3];
    const float* lin1_w = (const float*)d_in[4];
    const float* lin1_b = (const float*)d_in[5];
    const float* wa     = (const float*)d_in[6];
    const float* ba     = (const float*)d_in[7];
    const float* wb     = (const float*)d_in[8];
    const float* bb     = (const float*)d_in[9];
    const float* wo     = (const float*)d_in[10];
    const float* bo     = (const float*)d_in[11];
    float* out = (float*)d_out;

    float *D, *x2, *cat, *h1, *h2, *h3;
    int* idxp;
    cudaGetSymbolAddress((void**)&D,   g_D);
    cudaGetSymbolAddress((void**)&x2,  g_x2);
    cudaGetSymbolAddress((void**)&idxp,g_idx);
    cudaGetSymbolAddress((void**)&cat, g_cat);
    cudaGetSymbolAddress((void**)&h1,  g_h1);
    cudaGetSymbolAddress((void**)&h2,  g_h2);
    cudaGetSymbolAddress((void**)&h3,  g_h3);

    const dim3 gDist(NPTS / BN, NPTS / BM);

    // ---- layer 1: kNN on x (C=3), erode -> cat[:, 0:60]
    sqnorm_seq_kernel<<<32, 256>>>(x, 3, 3, x2);               // sequential
    gemm_kernel<true><<<gDist, 256>>>(x, 3, x, 3, nullptr, x2, D, NPTS, NPTS, 3);
    topk_kernel<<<NPTS / 8, 256>>>(D, idxp);
    erode_kernel<<<NPTS, 128>>>(x, 3, idxp, w1, cat, 420, 20, 3);

    // ---- layer 2: kNN on x1 (C=60), erode -> cat[:, 60:180]
    sqnorm_warp_kernel<<<NPTS / 8, 256>>>(cat, 420, 60, x2);   // warp tree
    gemm_kernel<true><<<gDist, 256>>>(cat, 420, cat, 420, nullptr, x2,
                                      D, NPTS, NPTS, 60);
    topk_kernel<<<NPTS / 8, 256>>>(D, idxp);
    erode_kernel<<<NPTS, 128>>>(cat, 420, idxp, w2, cat + 60, 420, 2, 60);

    // ---- layer 3: kNN on x2 (C=120), erode -> cat[:, 180:420]
    sqnorm_warp_kernel<<<NPTS / 8, 256>>>(cat + 60, 420, 120, x2);  // warp tree
    gemm_kernel<true><<<gDist, 256>>>(cat + 60, 420, cat + 60, 420, nullptr, x2,
                                      D, NPTS, NPTS, 120);
    topk_kernel<<<NPTS / 8, 256>>>(D, idxp);
    erode_kernel<<<NPTS, 128>>>(cat + 60, 420, idxp, w3, cat + 180, 420, 2, 120);

    // ---- MLP head
    gemm_kernel<false><<<dim3(1024 / BN, NPTS / BM), 256>>>(
        cat, 420, lin1_w, 1024, lin1_b, nullptr, h1, 1024, 1024, 420);
    gemm_kernel<false><<<dim3(2, NPTS / BM), 256>>>(
        h1, 1024, wa, 256, ba, nullptr, h2, 256, 256, 1024);
    gemm_kernel<false><<<dim3(1, NPTS / BM), 256>>>(
        h2, 256, wb, 128, bb, nullptr, h3, 128, 128, 256);

    head_kernel<<<NPTS, 128>>>(h3, wo, bo, out);
}

// round 9
// speedup vs baseline: 1.2743x; 1.2743x over previous
#include <cuda_runtime.h>
#include <math.h>
#include <float.h>

#define NPTS 8192
#define KNN  20

// ------------------------- scratch (__device__ globals, no allocation) ------
__device__ float g_D[(size_t)NPTS * NPTS];   // 256 MB dist matrix
__device__ float g_x2[NPTS];
__device__ int   g_idx[NPTS * KNN];
__device__ float g_cat[NPTS * 420];          // x1|x2|x3 concatenated (60|120|240)
__device__ float g_h1[NPTS * 1024];
__device__ float g_h2[NPTS * 256];
__device__ float g_h3[NPTS * 128];

// ------------------------- squared norms ------------------------------------
// Hybrid emulation of XLA GPU's reduction emitters for sum(x*x, -1), with
// SEPARATELY ROUNDED mul then add (NVVM default: no contraction):
//   C small (3)    : one thread per row, sequential ascending adds.
//   C large (60/120): one warp per row; lane-strided accumulate then
//                    full-warp shuffle-DOWN tree (offsets 16,8,4,2,1).
__global__ void sqnorm_seq_kernel(const float* __restrict__ X, int ld, int C,
                                  float* __restrict__ x2) {
    int i = blockIdx.x * blockDim.x + threadIdx.x;
    if (i >= NPTS) return;
    const float* r = X + (size_t)i * ld;
    float s = 0.f;
    for (int c = 0; c < C; ++c)
        s = __fadd_rn(s, __fmul_rn(r[c], r[c]));
    x2[i] = s;
}

__global__ void sqnorm_warp_kernel(const float* __restrict__ X, int ld, int C,
                                   float* __restrict__ x2) {
    const int lane = threadIdx.x & 31;
    const int row  = (blockIdx.x * blockDim.x + threadIdx.x) >> 5;
    if (row >= NPTS) return;

    const float* r = X + (size_t)row * ld;
    float s = 0.f;
    for (int c = lane; c < C; c += 32)
        s = __fadd_rn(s, __fmul_rn(r[c], r[c]));
#pragma unroll
    for (int off = 16; off > 0; off >>= 1)
        s = __fadd_rn(s, __shfl_down_sync(0xffffffffu, s, off));
    if (lane == 0) x2[row] = s;
}

#define BM 128
#define BN 128
#define BK 16

// ------------------------- symmetric pairwise distance ----------------------
// D[i,j] = (x2[i] + x2[j]) - 2*dot(X_i, X_j). D is bitwise symmetric:
// fmul commutative per product, ascending-k fadd/fma chain identical for
// (i,j) and (j,i), fadd(x2i,x2j) commutative. So compute only lower-triangle
// 128x128 blocks (by <= bx) and store each off-diagonal tile twice (normal +
// transposed). Transposed store is STG.128 over the thread's contiguous
// i-range -> full 32B sectors, no write amplification.
__global__ __launch_bounds__(256) void dist_sym_kernel(
    const float* __restrict__ X, int ld,
    const float* __restrict__ x2v,
    float* __restrict__ D, int K) {
    __shared__ float As[BK][BM + 4];
    __shared__ float Bs[BK][BN + 4];

    // linear block id -> (bx, by), by <= bx  (bx = row tile, by = col tile)
    const int t = blockIdx.x;
    int bx = (int)((sqrtf(8.f * (float)t + 1.f) - 1.f) * 0.5f);
    while ((bx + 1) * (bx + 2) / 2 <= t) ++bx;
    while (bx * (bx + 1) / 2 > t) --bx;
    const int by = t - bx * (bx + 1) / 2;

    const int i0 = bx * BM;
    const int j0 = by * BN;

    const int tid = threadIdx.x;          // 256
    const int tx = tid & 15;
    const int ty = tid >> 4;

    float acc[8][8];
#pragma unroll
    for (int u = 0; u < 8; ++u)
#pragma unroll
        for (int v = 0; v < 8; ++v) acc[u][v] = 0.f;

    for (int kk = 0; kk < K; kk += BK) {
        for (int e = tid; e < BM * BK; e += 256) {
            int r = e >> 4, c = e & 15;
            float v = 0.f;
            if (kk + c < K) v = X[(size_t)(i0 + r) * ld + kk + c];
            As[c][r] = v;
        }
        for (int e = tid; e < BN * BK; e += 256) {
            int r = e >> 4, c = e & 15;
            float v = 0.f;
            if (kk + c < K) v = X[(size_t)(j0 + r) * ld + kk + c];
            Bs[c][r] = v;
        }
        __syncthreads();

#pragma unroll
        for (int k = 0; k < BK; ++k) {
            float a[8], b[8];
            *(float4*)&a[0] = *(const float4*)&As[k][ty * 8];
            *(float4*)&a[4] = *(const float4*)&As[k][ty * 8 + 4];
            *(float4*)&b[0] = *(const float4*)&Bs[k][tx * 8];
            *(float4*)&b[4] = *(const float4*)&Bs[k][tx * 8 + 4];
#pragma unroll
            for (int u = 0; u < 8; ++u)
#pragma unroll
                for (int v = 0; v < 8; ++v)
                    acc[u][v] = fmaf(a[u], b[v], acc[u][v]);
        }
        __syncthreads();
    }

    // finalize: r(i,j) = fadd(x2i, x2j) - 2*acc  (2*acc exact)
    float res[8][8];
#pragma unroll
    for (int u = 0; u < 8; ++u) {
        int i = i0 + ty * 8 + u;
#pragma unroll
        for (int v = 0; v < 8; ++v) {
            int j = j0 + tx * 8 + v;
            float s = __fadd_rn(x2v[i], x2v[j]);
            res[u][v] = __fsub_rn(s, __fmul_rn(2.f, acc[u][v]));
        }
    }

    // normal store: rows i, contiguous j
#pragma unroll
    for (int u = 0; u < 8; ++u) {
        int i = i0 + ty * 8 + u;
        *(float4*)&D[(size_t)i * NPTS + j0 + tx * 8]     = *(float4*)&res[u][0];
        *(float4*)&D[(size_t)i * NPTS + j0 + tx * 8 + 4] = *(float4*)&res[u][4];
    }

    // transposed store (off-diagonal blocks): rows j, contiguous i
    if (bx != by) {
#pragma unroll
        for (int v = 0; v < 8; ++v) {
            int j = j0 + tx * 8 + v;
            float4 p0 = make_float4(res[0][v], res[1][v], res[2][v], res[3][v]);
            float4 p1 = make_float4(res[4][v], res[5][v], res[6][v], res[7][v]);
            *(float4*)&D[(size_t)j * NPTS + i0 + ty * 8]     = p0;
            *(float4*)&D[(size_t)j * NPTS + i0 + ty * 8 + 4] = p1;
        }
    }
}

// ------------------------- tiled fp32 GEMM (MLP) ----------------------------
// C[i,j] = relu(dot(A_i, W[:,j]) + bias[j]),  W row-major [K,N].
__global__ __launch_bounds__(256) void gemm_kernel(
    const float* __restrict__ A, int lda,
    const float* __restrict__ B, int ldb,
    const float* __restrict__ bias,
    float* __restrict__ Cout, int ldc,
    int N, int K) {
    __shared__ float As[BK][BM + 4];
    __shared__ float Bs[BK][BN + 4];

    const int tid = threadIdx.x;          // 256
    const int tx = tid & 15;
    const int ty = tid >> 4;
    const int i0 = blockIdx.y * BM;
    const int j0 = blockIdx.x * BN;

    float acc[8][8];
#pragma unroll
    for (int u = 0; u < 8; ++u)
#pragma unroll
        for (int v = 0; v < 8; ++v) acc[u][v] = 0.f;

    for (int kk = 0; kk < K; kk += BK) {
        for (int e = tid; e < BM * BK; e += 256) {
            int r = e >> 4, c = e & 15;
            float v = 0.f;
            if (kk + c < K) v = A[(size_t)(i0 + r) * lda + kk + c];
            As[c][r] = v;
        }
        for (int e = tid; e < BK * BN; e += 256) {
            int r = e >> 7, c = e & 127;
            float v = 0.f;
            if (kk + r < K && j0 + c < N)
                v = B[(size_t)(kk + r) * ldb + j0 + c];
            Bs[r][c] = v;
        }
        __syncthreads();

#pragma unroll
        for (int k = 0; k < BK; ++k) {
            float a[8], b[8];
            *(float4*)&a[0] = *(const float4*)&As[k][ty * 8];
            *(float4*)&a[4] = *(const float4*)&As[k][ty * 8 + 4];
            *(float4*)&b[0] = *(const float4*)&Bs[k][tx * 8];
            *(float4*)&b[4] = *(const float4*)&Bs[k][tx * 8 + 4];
#pragma unroll
            for (int u = 0; u < 8; ++u)
#pragma unroll
                for (int v = 0; v < 8; ++v)
                    acc[u][v] = fmaf(a[u], b[v], acc[u][v]);
        }
        __syncthreads();
    }

#pragma unroll
    for (int u = 0; u < 8; ++u) {
        int i = i0 + ty * 8 + u;
#pragma unroll
        for (int v = 0; v < 8; ++v) {
            int j = j0 + tx * 8 + v;
            if (j < N)
                Cout[(size_t)i * ldc + j] =
                    fmaxf(__fadd_rn(acc[u][v], bias[j]), 0.f);
        }
    }
}

// ------------------------- top-20 selection (warp per row) ------------------
// Reproduces jax.lax.top_k(-dist, 20) ordering: ascending dist, ties -> lower
// index first (candidates scanned in increasing j; strict '<' comparisons).
__global__ void topk_kernel(const float* __restrict__ D, int* __restrict__ out) {
    __shared__ float sd[8][KNN];
    __shared__ int   si[8][KNN];

    const int lane = threadIdx.x & 31;
    const int wloc = threadIdx.x >> 5;
    const int row  = (blockIdx.x * blockDim.x + threadIdx.x) >> 5;

    if (lane < KNN) { sd[wloc][lane] = FLT_MAX; si[wloc][lane] = 0x7fffffff; }
    __syncwarp();

    const float* r = D + (size_t)row * NPTS;
    float thresh = FLT_MAX;

    for (int base = 0; base < NPTS; base += 32) {
        float d = r[base + lane];
        unsigned m = __ballot_sync(0xffffffffu, d < thresh);
        while (m) {
            int src = __ffs(m) - 1;
            m &= m - 1;
            float dc = __shfl_sync(0xffffffffu, d, src);
            int   jc = base + src;
            if (lane == 0) {
                if (dc < sd[wloc][KNN - 1]) {
                    int p = KNN - 1;
                    while (p > 0 && sd[wloc][p - 1] > dc) {
                        sd[wloc][p] = sd[wloc][p - 1];
                        si[wloc][p] = si[wloc][p - 1];
                        --p;
                    }
                    sd[wloc][p] = dc;
                    si[wloc][p] = jc;
                }
            }
            __syncwarp();
            thresh = sd[wloc][KNN - 1];
        }
    }
    if (lane < KNN) out[row * KNN + lane] = si[wloc][lane];
}

// ------------------------- erosion EdgeConv ---------------------------------
// out[i, f*C + c] = min_k ( Xin[idx[i,k], c] - w[f,k,c] )   (sub + min: exact)
__global__ void erode_kernel(const float* __restrict__ Xin, int ldin,
                             const int* __restrict__ idx,
                             const float* __restrict__ w,
                             float* __restrict__ out, int ldout,
                             int F, int C) {
    __shared__ float nb[KNN * 120];    // max C = 120
    const int i = blockIdx.x;
    const int* ip = idx + i * KNN;

    for (int e = threadIdx.x; e < KNN * C; e += blockDim.x) {
        int k = e / C, c = e - k * C;
        nb[e] = Xin[(size_t)ip[k] * ldin + c];
    }
    __syncthreads();

    for (int e = threadIdx.x; e < F * C; e += blockDim.x) {
        int f = e / C, c = e - f * C;
        float mn = FLT_MAX;
        const float* wf = w + (size_t)f * KNN * C + c;
#pragma unroll 4
        for (int k = 0; k < KNN; ++k)
            mn = fminf(mn, __fsub_rn(nb[k * C + c], wf[k * C]));
        out[(size_t)i * ldout + e] = mn;
    }
}

// ------------------------- final linear + log_softmax -----------------------
__global__ void head_kernel(const float* __restrict__ H,
                            const float* __restrict__ wo,
                            const float* __restrict__ bo,
                            float* __restrict__ out) {
    __shared__ float h[128];
    __shared__ float lg[40];
    __shared__ float s_lse;
    const int i = blockIdx.x;
    const int t = threadIdx.x;              // 128 threads

    h[t] = H[(size_t)i * 128 + t];
    __syncthreads();

    if (t < 40) {
        float s = 0.f;
#pragma unroll 8
        for (int k = 0; k < 128; ++k) s = fmaf(h[k], wo[k * 40 + t], s);
        lg[t] = __fadd_rn(s, bo[t]);
    }
    __syncthreads();

    if (t == 0) {
        float m = -FLT_MAX;
        for (int n = 0; n < 40; ++n) m = fmaxf(m, lg[n]);
        float s = 0.f;
        for (int n = 0; n < 40; ++n) s = __fadd_rn(s, expf(__fsub_rn(lg[n], m)));
        s_lse = __fadd_rn(m, logf(s));
    }
    __syncthreads();

    if (t < 40) out[(size_t)i * 40 + t] = __fsub_rn(lg[t], s_lse);
}

// ------------------------- launch sequence ----------------------------------
extern "C" void kernel_launch(void* const* d_in, const int* in_sizes, int n_in,
                              void* d_out, int out_size) {
    const float* x      = (const float*)d_in[0];
    const float* w1     = (const float*)d_in[1];
    const float* w2     = (const float*)d_in[2];
    const float* w3     = (const float*)d_in[3];
    const float* lin1_w = (const float*)d_in[4];
    const float* lin1_b = (const float*)d_in[5];
    const float* wa     = (const float*)d_in[6];
    const float* ba     = (const float*)d_in[7];
    const float* wb     = (const float*)d_in[8];
    const float* bb     = (const float*)d_in[9];
    const float* wo     = (const float*)d_in[10];
    const float* bo     = (const float*)d_in[11];
    float* out = (float*)d_out;

    float *D, *x2, *cat, *h1, *h2, *h3;
    int* idxp;
    cudaGetSymbolAddress((void**)&D,   g_D);
    cudaGetSymbolAddress((void**)&x2,  g_x2);
    cudaGetSymbolAddress((void**)&idxp,g_idx);
    cudaGetSymbolAddress((void**)&cat, g_cat);
    cudaGetSymbolAddress((void**)&h1,  g_h1);
    cudaGetSymbolAddress((void**)&h2,  g_h2);
    cudaGetSymbolAddress((void**)&h3,  g_h3);

    const int NB = NPTS / BM;                 // 64 tiles per dim
    const int NTRI = NB * (NB + 1) / 2;       // 2080 lower-triangle blocks

    // ---- layer 1: kNN on x (C=3), erode -> cat[:, 0:60]
    sqnorm_seq_kernel<<<32, 256>>>(x, 3, 3, x2);
    dist_sym_kernel<<<NTRI, 256>>>(x, 3, x2, D, 3);
    topk_kernel<<<NPTS / 8, 256>>>(D, idxp);
    erode_kernel<<<NPTS, 128>>>(x, 3, idxp, w1, cat, 420, 20, 3);

    // ---- layer 2: kNN on x1 (C=60), erode -> cat[:, 60:180]
    sqnorm_warp_kernel<<<NPTS / 8, 256>>>(cat, 420, 60, x2);
    dist_sym_kernel<<<NTRI, 256>>>(cat, 420, x2, D, 60);
    topk_kernel<<<NPTS / 8, 256>>>(D, idxp);
    erode_kernel<<<NPTS, 128>>>(cat, 420, idxp, w2, cat + 60, 420, 2, 60);

    // ---- layer 3: kNN on x2 (C=120), erode -> cat[:, 180:420]
    sqnorm_warp_kernel<<<NPTS / 8, 256>>>(cat + 60, 420, 120, x2);
    dist_sym_kernel<<<NTRI, 256>>>(cat + 60, 420, x2, D, 120);
    topk_kernel<<<NPTS / 8, 256>>>(D, idxp);
    erode_kernel<<<NPTS, 128>>>(cat + 60, 420, idxp, w3, cat + 180, 420, 2, 120);

    // ---- MLP head
    gemm_kernel<<<dim3(1024 / BN, NPTS / BM), 256>>>(
        cat, 420, lin1_w, 1024, lin1_b, h1, 1024, 1024, 420);
    gemm_kernel<<<dim3(2, NPTS / BM), 256>>>(
        h1, 1024, wa, 256, ba, h2, 256, 256, 1024);
    gemm_kernel<<<dim3(1, NPTS / BM), 256>>>(
        h2, 256, wb, 128, bb, h3, 128, 128, 256);

    head_kernel<<<NPTS, 128>>>(h3, wo, bo, out);
}

// round 10
// speedup vs baseline: 1.4011x; 1.0995x over previous
#include <cuda_runtime.h>
#include <math.h>
#include <float.h>

#define NPTS 8192
#define KNN  20

// ------------------------- scratch (__device__ globals, no allocation) ------
__device__ float g_D[(size_t)NPTS * NPTS];   // 256 MB dist matrix
__device__ float g_x2[NPTS];
__device__ int   g_idx[NPTS * KNN];
__device__ float g_cat[NPTS * 420];          // x1|x2|x3 concatenated (60|120|240)
__device__ float g_h1[NPTS * 1024];
__device__ float g_h2[NPTS * 256];
__device__ float g_h3[NPTS * 128];

// ------------------------- squared norms ------------------------------------
// Frozen arithmetic recipe (matches reference bit-for-bit on ranking path):
//   C small (3)    : one thread per row, sequential separately-rounded adds.
//   C large (60/120): one warp per row; lane-strided accumulate then
//                    full-warp shuffle-DOWN tree (offsets 16,8,4,2,1).
__global__ void sqnorm_seq_kernel(const float* __restrict__ X, int ld, int C,
                                  float* __restrict__ x2) {
    int i = blockIdx.x * blockDim.x + threadIdx.x;
    if (i >= NPTS) return;
    const float* r = X + (size_t)i * ld;
    float s = 0.f;
    for (int c = 0; c < C; ++c)
        s = __fadd_rn(s, __fmul_rn(r[c], r[c]));
    x2[i] = s;
}

__global__ void sqnorm_warp_kernel(const float* __restrict__ X, int ld, int C,
                                   float* __restrict__ x2) {
    const int lane = threadIdx.x & 31;
    const int row  = (blockIdx.x * blockDim.x + threadIdx.x) >> 5;
    if (row >= NPTS) return;

    const float* r = X + (size_t)row * ld;
    float s = 0.f;
    for (int c = lane; c < C; c += 32)
        s = __fadd_rn(s, __fmul_rn(r[c], r[c]));
#pragma unroll
    for (int off = 16; off > 0; off >>= 1)
        s = __fadd_rn(s, __shfl_down_sync(0xffffffffu, s, off));
    if (lane == 0) x2[row] = s;
}

#define BM 128
#define BN 128
#define BK 16

// triangle decode: linear block id -> (bx, by), by <= bx
__device__ __forceinline__ void tri_decode(int t, int& bx, int& by) {
    bx = (int)((sqrtf(8.f * (float)t + 1.f) - 1.f) * 0.5f);
    while ((bx + 1) * (bx + 2) / 2 <= t) ++bx;
    while (bx * (bx + 1) / 2 > t) --bx;
    by = t - bx * (bx + 1) / 2;
}

// epilogue + symmetric dual store shared by both dist kernels
__device__ __forceinline__ void dist_store(float acc[8][8],
                                           const float* __restrict__ x2v,
                                           float* __restrict__ D,
                                           int i0, int j0, int tx, int ty,
                                           bool offdiag) {
    float res[8][8];
#pragma unroll
    for (int u = 0; u < 8; ++u) {
        int i = i0 + ty * 8 + u;
#pragma unroll
        for (int v = 0; v < 8; ++v) {
            int j = j0 + tx * 8 + v;
            float s = __fadd_rn(x2v[i], x2v[j]);
            res[u][v] = __fsub_rn(s, __fmul_rn(2.f, acc[u][v]));
        }
    }
#pragma unroll
    for (int u = 0; u < 8; ++u) {
        int i = i0 + ty * 8 + u;
        *(float4*)&D[(size_t)i * NPTS + j0 + tx * 8]     = *(float4*)&res[u][0];
        *(float4*)&D[(size_t)i * NPTS + j0 + tx * 8 + 4] = *(float4*)&res[u][4];
    }
    if (offdiag) {
#pragma unroll
        for (int v = 0; v < 8; ++v) {
            int j = j0 + tx * 8 + v;
            float4 p0 = make_float4(res[0][v], res[1][v], res[2][v], res[3][v]);
            float4 p1 = make_float4(res[4][v], res[5][v], res[6][v], res[7][v]);
            *(float4*)&D[(size_t)j * NPTS + i0 + ty * 8]     = p0;
            *(float4*)&D[(size_t)j * NPTS + i0 + ty * 8 + 4] = p1;
        }
    }
}

// ------------------------- K=3 specialized symmetric distance ---------------
// Exactly 3 ascending k-steps; bitwise identical to the padded BK=16 version
// (fma(0,0,acc) == acc, +0 preserved).
__global__ __launch_bounds__(256) void dist3_kernel(
    const float* __restrict__ X,
    const float* __restrict__ x2v,
    float* __restrict__ D) {
    __shared__ float A3[3][BM + 4];
    __shared__ float B3[3][BN + 4];

    int bx, by;
    tri_decode(blockIdx.x, bx, by);
    const int i0 = bx * BM, j0 = by * BN;
    const int tid = threadIdx.x;
    const int tx = tid & 15, ty = tid >> 4;

    if (tid < 128) {
        const float* ra = X + (size_t)(i0 + tid) * 3;
        const float* rb = X + (size_t)(j0 + tid) * 3;
#pragma unroll
        for (int c = 0; c < 3; ++c) { A3[c][tid] = ra[c]; B3[c][tid] = rb[c]; }
    }
    __syncthreads();

    float acc[8][8];
#pragma unroll
    for (int u = 0; u < 8; ++u)
#pragma unroll
        for (int v = 0; v < 8; ++v) acc[u][v] = 0.f;

#pragma unroll
    for (int k = 0; k < 3; ++k) {
        float a[8], b[8];
        *(float4*)&a[0] = *(const float4*)&A3[k][ty * 8];
        *(float4*)&a[4] = *(const float4*)&A3[k][ty * 8 + 4];
        *(float4*)&b[0] = *(const float4*)&B3[k][tx * 8];
        *(float4*)&b[4] = *(const float4*)&B3[k][tx * 8 + 4];
#pragma unroll
        for (int u = 0; u < 8; ++u)
#pragma unroll
            for (int v = 0; v < 8; ++v)
                acc[u][v] = fmaf(a[u], b[v], acc[u][v]);
    }

    dist_store(acc, x2v, D, i0, j0, tx, ty, bx != by);
}

// ------------------------- symmetric pairwise distance (double-buffered) ----
// D[i,j] = (x2[i] + x2[j]) - 2*dot(X_i, X_j); lower-triangle blocks only,
// dual store. dot = ascending-k single-accumulator FFMA chain (unchanged).
__global__ __launch_bounds__(256, 2) void dist_sym_kernel(
    const float* __restrict__ X, int ld,
    const float* __restrict__ x2v,
    float* __restrict__ D, int K) {
    __shared__ float As[2][BK][BM + 4];
    __shared__ float Bs[2][BK][BN + 4];

    int bx, by;
    tri_decode(blockIdx.x, bx, by);
    const int i0 = bx * BM, j0 = by * BN;
    const int tid = threadIdx.x;
    const int tx = tid & 15, ty = tid >> 4;

    float acc[8][8];
#pragma unroll
    for (int u = 0; u < 8; ++u)
#pragma unroll
        for (int v = 0; v < 8; ++v) acc[u][v] = 0.f;

    // prologue: tile 0
#pragma unroll
    for (int p = 0; p < 8; ++p) {
        int e = tid + 256 * p, r = e >> 4, c = e & 15;
        As[0][c][r] = (c < K) ? X[(size_t)(i0 + r) * ld + c] : 0.f;
        Bs[0][c][r] = (c < K) ? X[(size_t)(j0 + r) * ld + c] : 0.f;
    }
    __syncthreads();

    const int nt = (K + BK - 1) / BK;
    int buf = 0;
    for (int t = 1; t < nt; ++t) {
        const int kk = t * BK;
        float pa[8], pb[8];
#pragma unroll
        for (int p = 0; p < 8; ++p) {
            int e = tid + 256 * p, r = e >> 4, c = e & 15;
            pa[p] = (kk + c < K) ? X[(size_t)(i0 + r) * ld + kk + c] : 0.f;
            pb[p] = (kk + c < K) ? X[(size_t)(j0 + r) * ld + kk + c] : 0.f;
        }
#pragma unroll
        for (int k = 0; k < BK; ++k) {
            float a[8], b[8];
            *(float4*)&a[0] = *(const float4*)&As[buf][k][ty * 8];
            *(float4*)&a[4] = *(const float4*)&As[buf][k][ty * 8 + 4];
            *(float4*)&b[0] = *(const float4*)&Bs[buf][k][tx * 8];
            *(float4*)&b[4] = *(const float4*)&Bs[buf][k][tx * 8 + 4];
#pragma unroll
            for (int u = 0; u < 8; ++u)
#pragma unroll
                for (int v = 0; v < 8; ++v)
                    acc[u][v] = fmaf(a[u], b[v], acc[u][v]);
        }
#pragma unroll
        for (int p = 0; p < 8; ++p) {
            int e = tid + 256 * p, r = e >> 4, c = e & 15;
            As[buf ^ 1][c][r] = pa[p];
            Bs[buf ^ 1][c][r] = pb[p];
        }
        __syncthreads();
        buf ^= 1;
    }
    // last tile
#pragma unroll
    for (int k = 0; k < BK; ++k) {
        float a[8], b[8];
        *(float4*)&a[0] = *(const float4*)&As[buf][k][ty * 8];
        *(float4*)&a[4] = *(const float4*)&As[buf][k][ty * 8 + 4];
        *(float4*)&b[0] = *(const float4*)&Bs[buf][k][tx * 8];
        *(float4*)&b[4] = *(const float4*)&Bs[buf][k][tx * 8 + 4];
#pragma unroll
        for (int u = 0; u < 8; ++u)
#pragma unroll
            for (int v = 0; v < 8; ++v)
                acc[u][v] = fmaf(a[u], b[v], acc[u][v]);
    }

    dist_store(acc, x2v, D, i0, j0, tx, ty, bx != by);
}

// ------------------------- tiled fp32 GEMM (MLP, double-buffered) -----------
// C[i,j] = relu(dot(A_i, W[:,j]) + bias[j]),  W row-major [K,N].
__global__ __launch_bounds__(256, 2) void gemm_kernel(
    const float* __restrict__ A, int lda,
    const float* __restrict__ B, int ldb,
    const float* __restrict__ bias,
    float* __restrict__ Cout, int ldc,
    int N, int K) {
    __shared__ float As[2][BK][BM + 4];
    __shared__ float Bs[2][BK][BN + 4];

    const int tid = threadIdx.x;
    const int tx = tid & 15, ty = tid >> 4;
    const int i0 = blockIdx.y * BM;
    const int j0 = blockIdx.x * BN;

    float acc[8][8];
#pragma unroll
    for (int u = 0; u < 8; ++u)
#pragma unroll
        for (int v = 0; v < 8; ++v) acc[u][v] = 0.f;

    // prologue
#pragma unroll
    for (int p = 0; p < 8; ++p) {
        int e = tid + 256 * p;
        {
            int r = e >> 4, c = e & 15;
            As[0][c][r] = (c < K) ? A[(size_t)(i0 + r) * lda + c] : 0.f;
        }
        {
            int r = e >> 7, c = e & 127;
            Bs[0][r][c] = (r < K && j0 + c < N)
                              ? B[(size_t)r * ldb + j0 + c] : 0.f;
        }
    }
    __syncthreads();

    const int nt = (K + BK - 1) / BK;
    int buf = 0;
    for (int t = 1; t < nt; ++t) {
        const int kk = t * BK;
        float pa[8], pb[8];
#pragma unroll
        for (int p = 0; p < 8; ++p) {
            int e = tid + 256 * p;
            {
                int r = e >> 4, c = e & 15;
                pa[p] = (kk + c < K) ? A[(size_t)(i0 + r) * lda + kk + c] : 0.f;
            }
            {
                int r = e >> 7, c = e & 127;
                pb[p] = (kk + r < K && j0 + c < N)
                            ? B[(size_t)(kk + r) * ldb + j0 + c] : 0.f;
            }
        }
#pragma unroll
        for (int k = 0; k < BK; ++k) {
            float a[8], b[8];
            *(float4*)&a[0] = *(const float4*)&As[buf][k][ty * 8];
            *(float4*)&a[4] = *(const float4*)&As[buf][k][ty * 8 + 4];
            *(float4*)&b[0] = *(const float4*)&Bs[buf][k][tx * 8];
            *(float4*)&b[4] = *(const float4*)&Bs[buf][k][tx * 8 + 4];
#pragma unroll
            for (int u = 0; u < 8; ++u)
#pragma unroll
                for (int v = 0; v < 8; ++v)
                    acc[u][v] = fmaf(a[u], b[v], acc[u][v]);
        }
#pragma unroll
        for (int p = 0; p < 8; ++p) {
            int e = tid + 256 * p;
            { int r = e >> 4, c = e & 15;  As[buf ^ 1][c][r] = pa[p]; }
            { int r = e >> 7, c = e & 127; Bs[buf ^ 1][r][c] = pb[p]; }
        }
        __syncthreads();
        buf ^= 1;
    }
#pragma unroll
    for (int k = 0; k < BK; ++k) {
        float a[8], b[8];
        *(float4*)&a[0] = *(const float4*)&As[buf][k][ty * 8];
        *(float4*)&a[4] = *(const float4*)&As[buf][k][ty * 8 + 4];
        *(float4*)&b[0] = *(const float4*)&Bs[buf][k][tx * 8];
        *(float4*)&b[4] = *(const float4*)&Bs[buf][k][tx * 8 + 4];
#pragma unroll
        for (int u = 0; u < 8; ++u)
#pragma unroll
            for (int v = 0; v < 8; ++v)
                acc[u][v] = fmaf(a[u], b[v], acc[u][v]);
    }

#pragma unroll
    for (int u = 0; u < 8; ++u) {
        int i = i0 + ty * 8 + u;
#pragma unroll
        for (int v = 0; v < 8; ++v) {
            int j = j0 + tx * 8 + v;
            if (j < N)
                Cout[(size_t)i * ldc + j] =
                    fmaxf(__fadd_rn(acc[u][v], bias[j]), 0.f);
        }
    }
}

// ------------------------- top-20 selection (warp per row) ------------------
__global__ void topk_kernel(const float* __restrict__ D, int* __restrict__ out) {
    __shared__ float sd[8][KNN];
    __shared__ int   si[8][KNN];

    const int lane = threadIdx.x & 31;
    const int wloc = threadIdx.x >> 5;
    const int row  = (blockIdx.x * blockDim.x + threadIdx.x) >> 5;

    if (lane < KNN) { sd[wloc][lane] = FLT_MAX; si[wloc][lane] = 0x7fffffff; }
    __syncwarp();

    const float* r = D + (size_t)row * NPTS;
    float thresh = FLT_MAX;

    for (int base = 0; base < NPTS; base += 32) {
        float d = r[base + lane];
        unsigned m = __ballot_sync(0xffffffffu, d < thresh);
        while (m) {
            int src = __ffs(m) - 1;
            m &= m - 1;
            float dc = __shfl_sync(0xffffffffu, d, src);
            int   jc = base + src;
            if (lane == 0) {
                if (dc < sd[wloc][KNN - 1]) {
                    int p = KNN - 1;
                    while (p > 0 && sd[wloc][p - 1] > dc) {
                        sd[wloc][p] = sd[wloc][p - 1];
                        si[wloc][p] = si[wloc][p - 1];
                        --p;
                    }
                    sd[wloc][p] = dc;
                    si[wloc][p] = jc;
                }
            }
            __syncwarp();
            thresh = sd[wloc][KNN - 1];
        }
    }
    if (lane < KNN) out[row * KNN + lane] = si[wloc][lane];
}

// ------------------------- erosion EdgeConv ---------------------------------
__global__ void erode_kernel(const float* __restrict__ Xin, int ldin,
                             const int* __restrict__ idx,
                             const float* __restrict__ w,
                             float* __restrict__ out, int ldout,
                             int F, int C) {
    __shared__ float nb[KNN * 120];    // max C = 120
    const int i = blockIdx.x;
    const int* ip = idx + i * KNN;

    for (int e = threadIdx.x; e < KNN * C; e += blockDim.x) {
        int k = e / C, c = e - k * C;
        nb[e] = Xin[(size_t)ip[k] * ldin + c];
    }
    __syncthreads();

    for (int e = threadIdx.x; e < F * C; e += blockDim.x) {
        int f = e / C, c = e - f * C;
        float mn = FLT_MAX;
        const float* wf = w + (size_t)f * KNN * C + c;
#pragma unroll 4
        for (int k = 0; k < KNN; ++k)
            mn = fminf(mn, __fsub_rn(nb[k * C + c], wf[k * C]));
        out[(size_t)i * ldout + e] = mn;
    }
}

// ------------------------- final linear + log_softmax -----------------------
__global__ void head_kernel(const float* __restrict__ H,
                            const float* __restrict__ wo,
                            const float* __restrict__ bo,
                            float* __restrict__ out) {
    __shared__ float h[128];
    __shared__ float lg[40];
    __shared__ float s_lse;
    const int i = blockIdx.x;
    const int t = threadIdx.x;              // 128 threads

    h[t] = H[(size_t)i * 128 + t];
    __syncthreads();

    if (t < 40) {
        float s = 0.f;
#pragma unroll 8
        for (int k = 0; k < 128; ++k) s = fmaf(h[k], wo[k * 40 + t], s);
        lg[t] = __fadd_rn(s, bo[t]);
    }
    __syncthreads();

    if (t == 0) {
        float m = -FLT_MAX;
        for (int n = 0; n < 40; ++n) m = fmaxf(m, lg[n]);
        float s = 0.f;
        for (int n = 0; n < 40; ++n) s = __fadd_rn(s, expf(__fsub_rn(lg[n], m)));
        s_lse = __fadd_rn(m, logf(s));
    }
    __syncthreads();

    if (t < 40) out[(size_t)i * 40 + t] = __fsub_rn(lg[t], s_lse);
}

// ------------------------- launch sequence ----------------------------------
extern "C" void kernel_launch(void* const* d_in, const int* in_sizes, int n_in,
                              void* d_out, int out_size) {
    const float* x      = (const float*)d_in[0];
    const float* w1     = (const float*)d_in[1];
    const float* w2     = (const float*)d_in[2];
    const float* w3     = (const float*)d_in[3];
    const float* lin1_w = (const float*)d_in[4];
    const float* lin1_b = (const float*)d_in[5];
    const float* wa     = (const float*)d_in[6];
    const float* ba     = (const float*)d_in[7];
    const float* wb     = (const float*)d_in[8];
    const float* bb     = (const float*)d_in[9];
    const float* wo     = (const float*)d_in[10];
    const float* bo     = (const float*)d_in[11];
    float* out = (float*)d_out;

    float *D, *x2, *cat, *h1, *h2, *h3;
    int* idxp;
    cudaGetSymbolAddress((void**)&D,   g_D);
    cudaGetSymbolAddress((void**)&x2,  g_x2);
    cudaGetSymbolAddress((void**)&idxp,g_idx);
    cudaGetSymbolAddress((void**)&cat, g_cat);
    cudaGetSymbolAddress((void**)&h1,  g_h1);
    cudaGetSymbolAddress((void**)&h2,  g_h2);
    cudaGetSymbolAddress((void**)&h3,  g_h3);

    const int NB = NPTS / BM;                 // 64 tiles per dim
    const int NTRI = NB * (NB + 1) / 2;       // 2080 lower-triangle blocks

    // ---- layer 1: kNN on x (C=3), erode -> cat[:, 0:60]
    sqnorm_seq_kernel<<<32, 256>>>(x, 3, 3, x2);
    dist3_kernel<<<NTRI, 256>>>(x, x2, D);
    topk_kernel<<<NPTS / 8, 256>>>(D, idxp);
    erode_kernel<<<NPTS, 128>>>(x, 3, idxp, w1, cat, 420, 20, 3);

    // ---- layer 2: kNN on x1 (C=60), erode -> cat[:, 60:180]
    sqnorm_warp_kernel<<<NPTS / 8, 256>>>(cat, 420, 60, x2);
    dist_sym_kernel<<<NTRI, 256>>>(cat, 420, x2, D, 60);
    topk_kernel<<<NPTS / 8, 256>>>(D, idxp);
    erode_kernel<<<NPTS, 128>>>(cat, 420, idxp, w2, cat + 60, 420, 2, 60);

    // ---- layer 3: kNN on x2 (C=120), erode -> cat[:, 180:420]
    sqnorm_warp_kernel<<<NPTS / 8, 256>>>(cat + 60, 420, 120, x2);
    dist_sym_kernel<<<NTRI, 256>>>(cat + 60, 420, x2, D, 120);
    topk_kernel<<<NPTS / 8, 256>>>(D, idxp);
    erode_kernel<<<NPTS, 128>>>(cat + 60, 420, idxp, w3, cat + 180, 420, 2, 120);

    // ---- MLP head
    gemm_kernel<<<dim3(1024 / BN, NPTS / BM), 256>>>(
        cat, 420, lin1_w, 1024, lin1_b, h1, 1024, 1024, 420);
    gemm_kernel<<<dim3(2, NPTS / BM), 256>>>(
        h1, 1024, wa, 256, ba, h2, 256, 256, 1024);
    gemm_kernel<<<dim3(1, NPTS / BM), 256>>>(
        h2, 256, wb, 128, bb, h3, 128, 128, 256);

    head_kernel<<<NPTS, 128>>>(h3, wo, bo, out);
}